// round 15
// baseline (speedup 1.0000x reference)
#include <cuda_runtime.h>
#include <cuda_fp16.h>
#include <stdint.h>
#include <math.h>

#define BIGF 1000000000.0f
#define SIG 2144

// Cost matrix, fp16, SKEWED anti-diagonal layout:
// slot(b, sigma, r) at halves-address ((b*SIG + sigma)*1024 + r) holds
// C[r][kc] with kc = sigma - ((r>>2)&31). Zero-initialized; slots never
// written stay 0.0h (dtw's maskless induction relies on this).
static __device__ __align__(256) __half g_CH[70254592];   // 32*2144*1024
static __device__ float g_n1[32 * 1024];
static __device__ float g_n2[32 * 1024];

// ---------------------------------------------------------------------------
// Kernel 0: row squared norms (fp32). One warp per row.
// ---------------------------------------------------------------------------
__global__ __launch_bounds__(256) void norms_kernel(const float* __restrict__ s1,
                                                    const float* __restrict__ s2) {
    int b = blockIdx.y;
    const float* s = blockIdx.z ? s2 : s1;
    float* o = blockIdx.z ? g_n2 : g_n1;
    int lane = threadIdx.x & 31;
    int wid = threadIdx.x >> 5;
    int r = blockIdx.x * 8 + wid;
    const float4* p = (const float4*)(s + ((size_t)b * 1024 + r) * 128);
    float4 v = p[lane];
    float acc = v.x * v.x + v.y * v.y + v.z * v.z + v.w * v.w;
#pragma unroll
    for (int off = 16; off; off >>= 1)
        acc += __shfl_xor_sync(0xffffffffu, acc, off);
    if (lane == 0) o[b * 1024 + r] = acc;
}

// ---------------------------------------------------------------------------
// Kernel 1: cost matrix via tf32 mma.sync.m16n8k8 (R14 skeleton).
// grid (8, 8, 32); CTA tile 128(i) x 128(j); 8 warps 2x4; warp tile 64x32.
// K staged in 32-wide chunks in padded smem (stride 36: fragment LDS.32 bank
// index g*4+tg is conflict-free). RAW fp32 bits are staged and fed to the
// tf32 MMA (HW truncates to 19 bits) - no cvt.rna in the mainloop.
// __launch_bounds__(256, 2) caps regs at 128 so 2 CTAs are resident per SM:
// one CTA's staging LDG latency hides under the other's MMA mainloop.
// Epilogue sqrt(max(n1+n2-2dot,0)) -> fp16 staged in shared (stride 131),
// written out in the skewed sigma-layout with warp-level sl-bounds skipping.
// ---------------------------------------------------------------------------
#define MMA_TF32(C0, C1, C2, C3, A0, A1, A2, A3, B0, B1)                      \
    asm volatile(                                                              \
        "mma.sync.aligned.m16n8k8.row.col.f32.tf32.tf32.f32 "                  \
        "{%0,%1,%2,%3}, {%4,%5,%6,%7}, {%8,%9}, {%0,%1,%2,%3};"                \
        : "+f"(C0), "+f"(C1), "+f"(C2), "+f"(C3)                               \
        : "r"(A0), "r"(A1), "r"(A2), "r"(A3), "r"(B0), "r"(B1))

__global__ __launch_bounds__(256, 2) void cost_kernel(const float* __restrict__ s1,
                                                      const float* __restrict__ s2) {
    __shared__ float smem[9216];       // asmem[128][36] + bsmem[128][36]; reused as Ss(half)[128][131]
    float* asmem = smem;
    float* bsmem = smem + 4608;

    int b = blockIdx.z;
    int i0 = blockIdx.y * 128;
    int j0 = blockIdx.x * 128;
    int tid = threadIdx.x;
    int lane = tid & 31;
    int w = tid >> 5;
    int wm = w >> 2;
    int wn = w & 3;
    int g = lane >> 2;
    int tg = lane & 3;

    const float* A = s1 + ((size_t)b * 1024 + i0) * 128;
    const float* B = s2 + ((size_t)b * 1024 + j0) * 128;

    float c[4][4][4];
#pragma unroll
    for (int mt = 0; mt < 4; mt++)
#pragma unroll
        for (int nt = 0; nt < 4; nt++)
#pragma unroll
            for (int q = 0; q < 4; q++) c[mt][nt][q] = 0.0f;

    for (int kc0 = 0; kc0 < 128; kc0 += 32) {
        __syncthreads();
        // Stage A,B chunks (128 rows x 32 k each), raw fp32 bits (no cvt).
#pragma unroll
        for (int it = 0; it < 4; it++) {
            int u = tid + it * 256;
            int r = u >> 3;
            int c0 = (u & 7) * 4;
            *(float4*)&asmem[r * 36 + c0] = *(const float4*)&A[r * 128 + kc0 + c0];
            *(float4*)&bsmem[r * 36 + c0] = *(const float4*)&B[r * 128 + kc0 + c0];
        }
        __syncthreads();

#pragma unroll
        for (int ks = 0; ks < 4; ks++) {
            unsigned af[4][4], bf[4][2];
#pragma unroll
            for (int mt = 0; mt < 4; mt++) {
                int ar = wm * 64 + mt * 16;
                af[mt][0] = __float_as_uint(asmem[(ar + g) * 36 + ks * 8 + tg]);
                af[mt][1] = __float_as_uint(asmem[(ar + 8 + g) * 36 + ks * 8 + tg]);
                af[mt][2] = __float_as_uint(asmem[(ar + g) * 36 + ks * 8 + tg + 4]);
                af[mt][3] = __float_as_uint(asmem[(ar + 8 + g) * 36 + ks * 8 + tg + 4]);
            }
#pragma unroll
            for (int nt = 0; nt < 4; nt++) {
                int br = wn * 32 + nt * 8;
                bf[nt][0] = __float_as_uint(bsmem[(br + g) * 36 + ks * 8 + tg]);
                bf[nt][1] = __float_as_uint(bsmem[(br + g) * 36 + ks * 8 + tg + 4]);
            }
#pragma unroll
            for (int mt = 0; mt < 4; mt++)
#pragma unroll
                for (int nt = 0; nt < 4; nt++)
                    MMA_TF32(c[mt][nt][0], c[mt][nt][1], c[mt][nt][2], c[mt][nt][3],
                             af[mt][0], af[mt][1], af[mt][2], af[mt][3],
                             bf[nt][0], bf[nt][1]);
        }
    }
    __syncthreads();

    // Epilogue: fp16 distances into staging buffer Ss[128][131].
    __half* Ss = (__half*)smem;
#pragma unroll
    for (int mt = 0; mt < 4; mt++) {
        int r0 = wm * 64 + mt * 16 + g;
        float n1a = g_n1[b * 1024 + i0 + r0];
        float n1b = g_n1[b * 1024 + i0 + r0 + 8];
#pragma unroll
        for (int nt = 0; nt < 4; nt++) {
            int c0 = wn * 32 + nt * 8 + 2 * tg;
            float n2a = g_n2[b * 1024 + j0 + c0];
            float n2b = g_n2[b * 1024 + j0 + c0 + 1];
            float d00 = n1a + n2a - 2.0f * c[mt][nt][0];
            float d01 = n1a + n2b - 2.0f * c[mt][nt][1];
            float d10 = n1b + n2a - 2.0f * c[mt][nt][2];
            float d11 = n1b + n2b - 2.0f * c[mt][nt][3];
            Ss[r0 * 131 + c0]           = __float2half_rn(sqrtf(fmaxf(d00, 0.0f)));
            Ss[r0 * 131 + c0 + 1]       = __float2half_rn(sqrtf(fmaxf(d01, 0.0f)));
            Ss[(r0 + 8) * 131 + c0]     = __float2half_rn(sqrtf(fmaxf(d10, 0.0f)));
            Ss[(r0 + 8) * 131 + c0 + 1] = __float2half_rn(sqrtf(fmaxf(d11, 0.0f)));
        }
    }
    __syncthreads();

    // Skewed writeout with warp-level sl-bounds skipping.
    // sigma_loc = rloc + jloc + ((i0+rloc)>>2 & 31); valid jloc in [0,128).
    {
        int rloc = tid & 127;
        int sh = tid >> 7;
        int rterm = rloc + (((i0 + rloc) >> 2) & 31);
        int rmin = rterm, rmax = rterm;
#pragma unroll
        for (int off = 16; off; off >>= 1) {
            rmin = min(rmin, __shfl_xor_sync(0xffffffffu, rmin, off));
            rmax = max(rmax, __shfl_xor_sync(0xffffffffu, rmax, off));
        }
        int sl0 = (rmin & ~1) - 2;
        int sl1 = rmax + 127;
        for (int sl = sl0; sl <= sl1; sl += 2) {
            int sloc = sl + sh;
            int jloc = sloc - rterm;
            if (jloc >= 0 && jloc < 128) {
                size_t addr = ((size_t)b * SIG + (size_t)(i0 + j0 + sloc)) * 1024
                              + (size_t)(i0 + rloc);
                g_CH[addr] = Ss[rloc * 131 + jloc];
            }
        }
    }
}

// ---------------------------------------------------------------------------
// Kernel 2: DTW wavefront, lane-skewed pipeline (R14, unchanged). 256 threads,
// thread t owns DP rows 4t+1..4t+4 (register chain); lane l runs 1 diagonal
// behind lane l-1, reading lane-independent slot sigma = mb*32 + u (coalesced);
// shfl_up issued at step tau, consumed at tau+1. Warp w lags warp w-1 by 2
// intervals via triple-buffered edge[3][8][32] hoisted to registers at
// interval start. Out-of-band cost slots are 0.0h -> maskless BIGF
// propagation. Thread 255 (w=7, lane=31) hits k==2048 at (mb==64, u==29).
// ---------------------------------------------------------------------------
__global__ __launch_bounds__(256, 1) void dtw_kernel(float* __restrict__ out) {
    int b = blockIdx.x;
    int t = threadIdx.x;
    int lane = t & 31;
    int w = t >> 5;  // 8 warps

    __shared__ float edge[3][8][32];
    for (int s = t; s < 3 * 8 * 32; s += 256) (&edge[0][0][0])[s] = BIGF;
    __syncthreads();

    const uint2* C = (const uint2*)(g_CH + (size_t)b * SIG * 1024);

    float prev[4], prev2[4];
#pragma unroll
    for (int r = 0; r < 4; r++) { prev[r] = BIGF; prev2[r] = BIGF; }

    uint2 cb[32];
#pragma unroll
    for (int q = 0; q < 32; q++) cb[q] = __ldcs(&C[q * 256 + t]);

    float eup[32];
    float nextup = BIGF;
    float ans = BIGF;

    for (int m = 0; m < 79; ++m) {
        int mb = m - 2 * w;
        if (mb >= 0 && mb <= 64) {
            if (lane == 0) {
                if (w == 0) {
#pragma unroll
                    for (int u = 0; u < 32; u++) eup[u] = BIGF;
                    if (m == 0) eup[0] = 0.0f;      // D[0][0]=0 feeds k==2 only
                } else {
                    eup[0] = edge[(m + 1) % 3][w][31];         // produced at m-2
#pragma unroll
                    for (int u = 1; u < 32; u++)
                        eup[u] = edge[(m + 2) % 3][w][u - 1];  // produced at m-1
                }
            }
            const uint2* Cbase = C + (size_t)(mb * 32) * 256 + t;
#pragma unroll
            for (int u = 0; u < 32; ++u) {
                uint2 cw = cb[u];
                cb[u] = __ldcs(Cbase + (size_t)(u + 32) * 256);  // sigma+32 <= 2111 < SIG

                float2 f01 = __half22float2(*reinterpret_cast<__half2*>(&cw.x));
                float2 f23 = __half22float2(*reinterpret_cast<__half2*>(&cw.y));

                float up = (lane == 0) ? eup[u] : nextup;

                float nm0 = fminf(prev[0], prev2[0]);
                float nm1 = fminf(prev[1], prev2[1]);
                float nm2 = fminf(prev[2], prev2[2]);
                float nm3 = fminf(prev[3], prev2[3]);

                nextup = __shfl_up_sync(0xffffffffu, nm3, 1);
                if (lane == 31 && w < 7) edge[m % 3][w + 1][u] = nm3;

                float c0 = f01.x + fminf(prev[0], up);
                float c1 = f01.y + fminf(prev[1], nm0);
                float c2 = f23.x + fminf(prev[2], nm1);
                float c3 = f23.y + fminf(prev[3], nm2);

                if (u == 29 && mb == 64) ans = c3;  // thread 255: D[1024][1024] @ k=2048

                prev2[0] = prev[0]; prev[0] = c0;
                prev2[1] = prev[1]; prev[1] = c1;
                prev2[2] = prev[2]; prev[2] = c2;
                prev2[3] = prev[3]; prev[3] = c3;
            }
        }
        __syncthreads();
    }

    if (t == 255) {
        // softmax over a single weight == 1 exactly.
        float dist = ans * (1.0f / 2048.0f);
        out[b] = 1.0f / (1.0f + dist);
    }
}

// ---------------------------------------------------------------------------
extern "C" void kernel_launch(void* const* d_in, const int* in_sizes, int n_in,
                              void* d_out, int out_size) {
    const float* seq1 = (const float*)d_in[0];
    const float* seq2 = (const float*)d_in[1];
    // d_in[2] = scale_weights (1 elem): softmax of a single weight is exactly 1.0.
    float* out = (float*)d_out;

    dim3 gN(128, 32, 2);
    norms_kernel<<<gN, 256>>>(seq1, seq2);

    dim3 gC(8, 8, 32);
    cost_kernel<<<gC, 256>>>(seq1, seq2);

    dtw_kernel<<<32, 256>>>(out);
}

// round 16
// speedup vs baseline: 1.0778x; 1.0778x over previous
#include <cuda_runtime.h>
#include <cuda_fp16.h>
#include <cuda_bf16.h>
#include <stdint.h>
#include <math.h>

#define BIGF 1000000000.0f
#define SIG 2144

// Cost matrix, fp16, SKEWED anti-diagonal layout:
// slot(b, sigma, r) at halves-address ((b*SIG + sigma)*1024 + r) holds
// C[r][kc] with kc = sigma - ((r>>2)&31). Zero-initialized; slots never
// written stay 0.0h (dtw's maskless induction relies on this).
static __device__ __align__(256) __half g_CH[70254592];   // 32*2144*1024
static __device__ float g_n1[32 * 1024];
static __device__ float g_n2[32 * 1024];

// ---------------------------------------------------------------------------
// Kernel 0: row squared norms (fp32). One warp per row.
// ---------------------------------------------------------------------------
__global__ __launch_bounds__(256) void norms_kernel(const float* __restrict__ s1,
                                                    const float* __restrict__ s2) {
    int b = blockIdx.y;
    const float* s = blockIdx.z ? s2 : s1;
    float* o = blockIdx.z ? g_n2 : g_n1;
    int lane = threadIdx.x & 31;
    int wid = threadIdx.x >> 5;
    int r = blockIdx.x * 8 + wid;
    const float4* p = (const float4*)(s + ((size_t)b * 1024 + r) * 128);
    float4 v = p[lane];
    float acc = v.x * v.x + v.y * v.y + v.z * v.z + v.w * v.w;
#pragma unroll
    for (int off = 16; off; off >>= 1)
        acc += __shfl_xor_sync(0xffffffffu, acc, off);
    if (lane == 0) o[b * 1024 + r] = acc;
}

// ---------------------------------------------------------------------------
// Kernel 1: cost matrix via bf16 mma.sync.m16n8k16 (halves MMA count, LDS
// count, smem bytes and staging traffic vs the tf32 m16n8k8 version; C
// accumulator layout is identical, so epilogue/writeout are unchanged).
// grid (8, 8, 32); CTA tile 128(i) x 128(j); 8 warps 2x4; warp tile 64x32.
// K staged in 64-wide chunks as packed bf16x2 words, row stride 36 words:
// fragment LDS bank index 4g+tg (+4) is conflict-free. Norms stay fp32.
// Epilogue sqrt(max(n1+n2-2dot,0)) -> fp16 staged in shared (stride 131),
// written out in the skewed sigma-layout with warp-level sl-bounds skipping.
// ---------------------------------------------------------------------------
#define MMA_BF16(C0, C1, C2, C3, A0, A1, A2, A3, B0, B1)                      \
    asm volatile(                                                              \
        "mma.sync.aligned.m16n8k16.row.col.f32.bf16.bf16.f32 "                 \
        "{%0,%1,%2,%3}, {%4,%5,%6,%7}, {%8,%9}, {%0,%1,%2,%3};"                \
        : "+f"(C0), "+f"(C1), "+f"(C2), "+f"(C3)                               \
        : "r"(A0), "r"(A1), "r"(A2), "r"(A3), "r"(B0), "r"(B1))

__device__ __forceinline__ unsigned pack_bf16x2(float lo, float hi) {
    unsigned d;
    asm("cvt.rn.bf16x2.f32 %0, %1, %2;" : "=r"(d) : "f"(hi), "f"(lo));
    return d;
}

__global__ __launch_bounds__(256) void cost_kernel(const float* __restrict__ s1,
                                                   const float* __restrict__ s2) {
    // asmem[128][36] + bsmem[128][36] words (bf16x2) = 36.9 KB;
    // reused as Ss(half)[128][131] (33.5 KB) in the epilogue.
    __shared__ unsigned smem[9216];
    unsigned* asmem = smem;
    unsigned* bsmem = smem + 4608;

    int b = blockIdx.z;
    int i0 = blockIdx.y * 128;
    int j0 = blockIdx.x * 128;
    int tid = threadIdx.x;
    int lane = tid & 31;
    int w = tid >> 5;
    int wm = w >> 2;
    int wn = w & 3;
    int g = lane >> 2;
    int tg = lane & 3;

    const float* A = s1 + ((size_t)b * 1024 + i0) * 128;
    const float* B = s2 + ((size_t)b * 1024 + j0) * 128;

    float c[4][4][4];
#pragma unroll
    for (int mt = 0; mt < 4; mt++)
#pragma unroll
        for (int nt = 0; nt < 4; nt++)
#pragma unroll
            for (int q = 0; q < 4; q++) c[mt][nt][q] = 0.0f;

    for (int kc0 = 0; kc0 < 128; kc0 += 64) {
        __syncthreads();
        // Stage A,B chunks (128 rows x 64 k) as packed bf16x2.
        // Thread u (u = tid + it*256, it<4) handles row r = u>>3, 8 floats at
        // col (u&7)*8 -> 4 words at word-offset r*36 + (u&7)*4.
#pragma unroll
        for (int it = 0; it < 4; it++) {
            int u = tid + it * 256;
            int r = u >> 3;
            int c0 = (u & 7) * 8;
            float4 a0 = *(const float4*)&A[r * 128 + kc0 + c0];
            float4 a1 = *(const float4*)&A[r * 128 + kc0 + c0 + 4];
            float4 b0 = *(const float4*)&B[r * 128 + kc0 + c0];
            float4 b1 = *(const float4*)&B[r * 128 + kc0 + c0 + 4];
            uint2 aw0 = make_uint2(pack_bf16x2(a0.x, a0.y), pack_bf16x2(a0.z, a0.w));
            uint2 aw1 = make_uint2(pack_bf16x2(a1.x, a1.y), pack_bf16x2(a1.z, a1.w));
            uint2 bw0 = make_uint2(pack_bf16x2(b0.x, b0.y), pack_bf16x2(b0.z, b0.w));
            uint2 bw1 = make_uint2(pack_bf16x2(b1.x, b1.y), pack_bf16x2(b1.z, b1.w));
            int wo = r * 36 + (u & 7) * 4;
            *(uint2*)&asmem[wo]     = aw0;
            *(uint2*)&asmem[wo + 2] = aw1;
            *(uint2*)&bsmem[wo]     = bw0;
            *(uint2*)&bsmem[wo + 2] = bw1;
        }
        __syncthreads();

        // 4 k-steps of 16 per chunk. Fragment words (bf16x2, word = k/2):
        // A: a0 = [row g,    k-octet 0] word (ar+g)*36 + ks*8 + tg
        //    a1 = [row g+8,  k-octet 0]
        //    a2 = [row g,    k-octet 1] (+4 words)
        //    a3 = [row g+8,  k-octet 1]
        // B: b0 = [n g, k-octet 0], b1 = [n g, k-octet 1]
#pragma unroll
        for (int ks = 0; ks < 4; ks++) {
            unsigned af[4][4], bf[4][2];
#pragma unroll
            for (int mt = 0; mt < 4; mt++) {
                int ar = wm * 64 + mt * 16;
                af[mt][0] = asmem[(ar + g) * 36 + ks * 8 + tg];
                af[mt][1] = asmem[(ar + 8 + g) * 36 + ks * 8 + tg];
                af[mt][2] = asmem[(ar + g) * 36 + ks * 8 + tg + 4];
                af[mt][3] = asmem[(ar + 8 + g) * 36 + ks * 8 + tg + 4];
            }
#pragma unroll
            for (int nt = 0; nt < 4; nt++) {
                int br = wn * 32 + nt * 8;
                bf[nt][0] = bsmem[(br + g) * 36 + ks * 8 + tg];
                bf[nt][1] = bsmem[(br + g) * 36 + ks * 8 + tg + 4];
            }
#pragma unroll
            for (int mt = 0; mt < 4; mt++)
#pragma unroll
                for (int nt = 0; nt < 4; nt++)
                    MMA_BF16(c[mt][nt][0], c[mt][nt][1], c[mt][nt][2], c[mt][nt][3],
                             af[mt][0], af[mt][1], af[mt][2], af[mt][3],
                             bf[nt][0], bf[nt][1]);
        }
    }
    __syncthreads();

    // Epilogue: fp16 distances into staging buffer Ss[128][131].
    __half* Ss = (__half*)smem;
#pragma unroll
    for (int mt = 0; mt < 4; mt++) {
        int r0 = wm * 64 + mt * 16 + g;
        float n1a = g_n1[b * 1024 + i0 + r0];
        float n1b = g_n1[b * 1024 + i0 + r0 + 8];
#pragma unroll
        for (int nt = 0; nt < 4; nt++) {
            int c0 = wn * 32 + nt * 8 + 2 * tg;
            float n2a = g_n2[b * 1024 + j0 + c0];
            float n2b = g_n2[b * 1024 + j0 + c0 + 1];
            float d00 = n1a + n2a - 2.0f * c[mt][nt][0];
            float d01 = n1a + n2b - 2.0f * c[mt][nt][1];
            float d10 = n1b + n2a - 2.0f * c[mt][nt][2];
            float d11 = n1b + n2b - 2.0f * c[mt][nt][3];
            Ss[r0 * 131 + c0]           = __float2half_rn(sqrtf(fmaxf(d00, 0.0f)));
            Ss[r0 * 131 + c0 + 1]       = __float2half_rn(sqrtf(fmaxf(d01, 0.0f)));
            Ss[(r0 + 8) * 131 + c0]     = __float2half_rn(sqrtf(fmaxf(d10, 0.0f)));
            Ss[(r0 + 8) * 131 + c0 + 1] = __float2half_rn(sqrtf(fmaxf(d11, 0.0f)));
        }
    }
    __syncthreads();

    // Skewed writeout with warp-level sl-bounds skipping.
    // sigma_loc = rloc + jloc + ((i0+rloc)>>2 & 31); valid jloc in [0,128).
    {
        int rloc = tid & 127;
        int sh = tid >> 7;
        int rterm = rloc + (((i0 + rloc) >> 2) & 31);
        int rmin = rterm, rmax = rterm;
#pragma unroll
        for (int off = 16; off; off >>= 1) {
            rmin = min(rmin, __shfl_xor_sync(0xffffffffu, rmin, off));
            rmax = max(rmax, __shfl_xor_sync(0xffffffffu, rmax, off));
        }
        int sl0 = (rmin & ~1) - 2;
        int sl1 = rmax + 127;
        for (int sl = sl0; sl <= sl1; sl += 2) {
            int sloc = sl + sh;
            int jloc = sloc - rterm;
            if (jloc >= 0 && jloc < 128) {
                size_t addr = ((size_t)b * SIG + (size_t)(i0 + j0 + sloc)) * 1024
                              + (size_t)(i0 + rloc);
                g_CH[addr] = Ss[rloc * 131 + jloc];
            }
        }
    }
}

// ---------------------------------------------------------------------------
// Kernel 2: DTW wavefront, lane-skewed pipeline (R14, unchanged). 256 threads,
// thread t owns DP rows 4t+1..4t+4 (register chain); lane l runs 1 diagonal
// behind lane l-1, reading lane-independent slot sigma = mb*32 + u (coalesced);
// shfl_up issued at step tau, consumed at tau+1. Warp w lags warp w-1 by 2
// intervals via triple-buffered edge[3][8][32] hoisted to registers at
// interval start. Out-of-band cost slots are 0.0h -> maskless BIGF
// propagation. Thread 255 (w=7, lane=31) hits k==2048 at (mb==64, u==29).
// ---------------------------------------------------------------------------
__global__ __launch_bounds__(256, 1) void dtw_kernel(float* __restrict__ out) {
    int b = blockIdx.x;
    int t = threadIdx.x;
    int lane = t & 31;
    int w = t >> 5;  // 8 warps

    __shared__ float edge[3][8][32];
    for (int s = t; s < 3 * 8 * 32; s += 256) (&edge[0][0][0])[s] = BIGF;
    __syncthreads();

    const uint2* C = (const uint2*)(g_CH + (size_t)b * SIG * 1024);

    float prev[4], prev2[4];
#pragma unroll
    for (int r = 0; r < 4; r++) { prev[r] = BIGF; prev2[r] = BIGF; }

    uint2 cb[32];
#pragma unroll
    for (int q = 0; q < 32; q++) cb[q] = __ldcs(&C[q * 256 + t]);

    float eup[32];
    float nextup = BIGF;
    float ans = BIGF;

    for (int m = 0; m < 79; ++m) {
        int mb = m - 2 * w;
        if (mb >= 0 && mb <= 64) {
            if (lane == 0) {
                if (w == 0) {
#pragma unroll
                    for (int u = 0; u < 32; u++) eup[u] = BIGF;
                    if (m == 0) eup[0] = 0.0f;      // D[0][0]=0 feeds k==2 only
                } else {
                    eup[0] = edge[(m + 1) % 3][w][31];         // produced at m-2
#pragma unroll
                    for (int u = 1; u < 32; u++)
                        eup[u] = edge[(m + 2) % 3][w][u - 1];  // produced at m-1
                }
            }
            const uint2* Cbase = C + (size_t)(mb * 32) * 256 + t;
#pragma unroll
            for (int u = 0; u < 32; ++u) {
                uint2 cw = cb[u];
                cb[u] = __ldcs(Cbase + (size_t)(u + 32) * 256);  // sigma+32 <= 2111 < SIG

                float2 f01 = __half22float2(*reinterpret_cast<__half2*>(&cw.x));
                float2 f23 = __half22float2(*reinterpret_cast<__half2*>(&cw.y));

                float up = (lane == 0) ? eup[u] : nextup;

                float nm0 = fminf(prev[0], prev2[0]);
                float nm1 = fminf(prev[1], prev2[1]);
                float nm2 = fminf(prev[2], prev2[2]);
                float nm3 = fminf(prev[3], prev2[3]);

                nextup = __shfl_up_sync(0xffffffffu, nm3, 1);
                if (lane == 31 && w < 7) edge[m % 3][w + 1][u] = nm3;

                float c0 = f01.x + fminf(prev[0], up);
                float c1 = f01.y + fminf(prev[1], nm0);
                float c2 = f23.x + fminf(prev[2], nm1);
                float c3 = f23.y + fminf(prev[3], nm2);

                if (u == 29 && mb == 64) ans = c3;  // thread 255: D[1024][1024] @ k=2048

                prev2[0] = prev[0]; prev[0] = c0;
                prev2[1] = prev[1]; prev[1] = c1;
                prev2[2] = prev[2]; prev[2] = c2;
                prev2[3] = prev[3]; prev[3] = c3;
            }
        }
        __syncthreads();
    }

    if (t == 255) {
        // softmax over a single weight == 1 exactly.
        float dist = ans * (1.0f / 2048.0f);
        out[b] = 1.0f / (1.0f + dist);
    }
}

// ---------------------------------------------------------------------------
extern "C" void kernel_launch(void* const* d_in, const int* in_sizes, int n_in,
                              void* d_out, int out_size) {
    const float* seq1 = (const float*)d_in[0];
    const float* seq2 = (const float*)d_in[1];
    // d_in[2] = scale_weights (1 elem): softmax of a single weight is exactly 1.0.
    float* out = (float*)d_out;

    dim3 gN(128, 32, 2);
    norms_kernel<<<gN, 256>>>(seq1, seq2);

    dim3 gC(8, 8, 32);
    cost_kernel<<<gC, 256>>>(seq1, seq2);

    dtw_kernel<<<32, 256>>>(out);
}